// round 1
// baseline (speedup 1.0000x reference)
#include <cuda_runtime.h>
#include <math.h>

#define NS 64          // coarse samples
#define NF 128         // fine samples
#define NC 192         // combined
#define WPB 8          // warps per block
#define FULL 0xffffffffu

__global__ __launch_bounds__(WPB * 32)
void pdf_sampler_kernel(const float* __restrict__ near_, const float* __restrict__ far_,
                        const float* __restrict__ density, const float* __restrict__ rgb,
                        float* __restrict__ zs_out, float* __restrict__ rgb_out,
                        float* __restrict__ depth_out, float* __restrict__ acc_out,
                        int B)
{
    __shared__ float s_mids[WPB][NS];
    __shared__ float s_cdf [WPB][NS];
    __shared__ float s_fine[WPB][NF];

    const int warp = threadIdx.x >> 5;
    const int lane = threadIdx.x & 31;
    const int ray  = blockIdx.x * WPB + warp;
    if (ray >= B) return;

    const float nr = near_[ray];
    const float fr = far_[ray];
    const float delta = (fr - nr) * (1.0f / NS);

    // ---- load density (2 elems per lane, coalesced float2) ----
    const float2 dv = *reinterpret_cast<const float2*>(density + (size_t)ray * NS + 2 * lane);
    const float e0 = dv.x * delta;
    const float e1 = dv.y * delta;

    // ---- warp inclusive prefix sum over 64 elems (pair per lane) ----
    const float ps = e0 + e1;
    float s = ps;
    #pragma unroll
    for (int off = 1; off < 32; off <<= 1) {
        float v = __shfl_up_sync(FULL, s, off);
        if (lane >= off) s += v;
    }
    const float excl = s - ps;           // exclusive prefix at elem 2*lane
    const float c0 = excl + e0;          // inclusive at 2*lane
    const float c1 = excl + ps;          // inclusive at 2*lane+1

    // weights: w_i = T_i * (1 - exp(-x_i)), T_i = exp(-prefix)
    const float T0 = __expf(-excl);
    const float a0 = -expm1f(-e0);
    const float w0 = T0 * a0;
    const float Tm = T0 - w0;            // = T0 * exp(-e0)
    const float a1 = -expm1f(-e1);
    const float w1 = Tm * a1;

    // mids
    const float m0 = fmaf((float)(2 * lane)     + 0.5f, delta, nr);
    const float m1 = fmaf((float)(2 * lane + 1) + 0.5f, delta, nr);

    // ---- rgb loads (6 contiguous floats per lane) ----
    const float* rrow = rgb + (size_t)ray * (NS * 3) + 6 * lane;
    const float2 ra = *reinterpret_cast<const float2*>(rrow + 0);
    const float2 rb = *reinterpret_cast<const float2*>(rrow + 2);
    const float2 rc = *reinterpret_cast<const float2*>(rrow + 4);
    // rgb0 = (ra.x, ra.y, rb.x), rgb1 = (rb.y, rc.x, rc.y)

    // ---- reductions: acc, depth numerator, rgb sums ----
    float wsum = w0 + w1;
    float dsum = w0 * m0 + w1 * m1;
    float rs   = w0 * ra.x + w1 * rb.y;
    float gs   = w0 * ra.y + w1 * rc.x;
    float bs   = w0 * rb.x + w1 * rc.y;
    #pragma unroll
    for (int off = 16; off >= 1; off >>= 1) {
        wsum += __shfl_xor_sync(FULL, wsum, off);
        dsum += __shfl_xor_sync(FULL, dsum, off);
        rs   += __shfl_xor_sync(FULL, rs,   off);
        gs   += __shfl_xor_sync(FULL, gs,   off);
        bs   += __shfl_xor_sync(FULL, bs,   off);
    }

    // ---- cdf (accurate cumulative weights via expm1) ----
    const float inv = 1.0f / (wsum + 1e-6f);
    const float cw0 = -expm1f(-c0);      // sum of weights up to incl 2*lane
    const float cw1 = -expm1f(-c1);
    float* cdfr  = s_cdf[warp];
    float* midr  = s_mids[warp];
    float* finer = s_fine[warp];
    cdfr[2 * lane]     = cw0 * inv;
    cdfr[2 * lane + 1] = cw1 * inv;
    midr[2 * lane]     = m0;
    midr[2 * lane + 1] = m1;
    __syncwarp();

    // ---- hierarchical sampling: 4 fine samples per lane ----
    const float ustep = 0.9f / 127.0f;
    float fvals[4];
    int   fidx[4];
    #pragma unroll
    for (int j = 0; j < 4; ++j) {
        const int k = lane + 32 * j;
        const float u = fmaf((float)k, ustep, 0.05f);
        // searchsorted right: count of cdf[i] <= u, range 0..64
        int pos = 0;
        #pragma unroll
        for (int st = 64; st >= 1; st >>= 1) {
            int np = pos + st;
            if (np <= NS && cdfr[np - 1] <= u) pos = np;
        }
        const int below = max(pos - 1, 0);
        const int above = min(pos, NS - 1);
        const float cb = cdfr[below];
        const float ca = cdfr[above];
        float denom = ca - cb;
        if (denom < 1e-5f) denom = 1.0f;
        const float t = (u - cb) / denom;
        const float bb = midr[below];
        const float ba = midr[above];
        const float fz = fmaf(t, ba - bb, bb);
        fvals[j] = fz;
        fidx[j]  = k;
        finer[k] = fz;
    }
    __syncwarp();

    // ---- merge (ranks form an exact permutation of 0..191) ----
    float* zrow = zs_out + (size_t)ray * NC;

    // mids: rank = i + (# fine < mid)
    #pragma unroll
    for (int j = 0; j < 2; ++j) {
        const int i = 2 * lane + j;
        const float v = (j == 0) ? m0 : m1;
        int pos = 0;
        #pragma unroll
        for (int st = 128; st >= 1; st >>= 1) {
            int np = pos + st;
            if (np <= NF && finer[np - 1] < v) pos = np;
        }
        zrow[i + pos] = v;
    }
    // fine: rank = k + (# mids <= fine)
    #pragma unroll
    for (int j = 0; j < 4; ++j) {
        const float v = fvals[j];
        int pos = 0;
        #pragma unroll
        for (int st = 64; st >= 1; st >>= 1) {
            int np = pos + st;
            if (np <= NS && midr[np - 1] <= v) pos = np;
        }
        zrow[fidx[j] + pos] = v;
    }

    // ---- scalar outputs ----
    if (lane == 0) {
        rgb_out[(size_t)ray * 3 + 0] = rs;
        rgb_out[(size_t)ray * 3 + 1] = gs;
        rgb_out[(size_t)ray * 3 + 2] = bs;
        depth_out[ray] = dsum / (wsum + 1e-8f);
        acc_out[ray]   = wsum;
    }
}

extern "C" void kernel_launch(void* const* d_in, const int* in_sizes, int n_in,
                              void* d_out, int out_size)
{
    const float* near_   = (const float*)d_in[0];
    const float* far_    = (const float*)d_in[1];
    const float* density = (const float*)d_in[2];
    const float* rgb     = (const float*)d_in[3];
    const int B = in_sizes[0];

    float* out   = (float*)d_out;
    float* zs    = out;                       // B * 192
    float* rgbo  = zs + (size_t)B * NC;       // B * 3
    float* depth = rgbo + (size_t)B * 3;      // B
    float* acc   = depth + B;                 // B

    const int blocks = (B + WPB - 1) / WPB;
    pdf_sampler_kernel<<<blocks, WPB * 32>>>(near_, far_, density, rgb,
                                             zs, rgbo, depth, acc, B);
}

// round 2
// speedup vs baseline: 1.0181x; 1.0181x over previous
#include <cuda_runtime.h>
#include <math.h>

#define NS 64          // coarse samples
#define NF 128         // fine samples
#define NC 192         // combined
#define WPB 8          // warps per block
#define FULL 0xffffffffu

// #{k in [0,128) : u_k < x}, u_k = 0.05 + k * (0.9/127)
__device__ __forceinline__ int count_u(float x) {
    float T = (x - 0.05f) * (127.0f / 0.9f);
    int c = (int)ceilf(T);
    return min(max(c, 0), NF);
}

__global__ __launch_bounds__(WPB * 32)
void pdf_sampler_kernel(const float* __restrict__ near_, const float* __restrict__ far_,
                        const float* __restrict__ density, const float* __restrict__ rgb,
                        float* __restrict__ zs_out, float* __restrict__ rgb_out,
                        float* __restrict__ depth_out, float* __restrict__ acc_out,
                        int B)
{
    const int warp = threadIdx.x >> 5;
    const int lane = threadIdx.x & 31;
    const int ray  = blockIdx.x * WPB + warp;
    if (ray >= B) return;

    const float nr = near_[ray];
    const float fr = far_[ray];
    const float delta = (fr - nr) * (1.0f / NS);

    // ---- density: 2 elems per lane, coalesced float2 ----
    const float2 dv = *reinterpret_cast<const float2*>(density + (size_t)ray * NS + 2 * lane);
    const float e0 = dv.x * delta;
    const float e1 = dv.y * delta;

    // ---- warp inclusive prefix sum of optical depth (pair per lane) ----
    const float ps = e0 + e1;
    float s = ps;
    #pragma unroll
    for (int off = 1; off < 32; off <<= 1) {
        float v = __shfl_up_sync(FULL, s, off);
        if (lane >= off) s += v;
    }
    const float excl = s - ps;           // cum optical depth before elem 2*lane
    const float c0 = excl + e0;          // inclusive at 2*lane
    const float c1 = excl + ps;          // inclusive at 2*lane+1

    // weights: w_i = T_i * (1 - exp(-x_i))
    const float T0 = __expf(-excl);
    const float w0 = T0 * (1.0f - __expf(-e0));
    const float Tm = T0 - w0;            // = T0 * exp(-e0)
    const float w1 = Tm * (1.0f - __expf(-e1));

    // analytic mids
    const float m0 = fmaf((float)(2 * lane) + 0.5f, delta, nr);
    const float m1 = m0 + delta;

    // ---- rgb loads (6 contiguous floats per lane, coalesced) ----
    const float* rrow = rgb + (size_t)ray * (NS * 3) + 6 * lane;
    const float2 ra = *reinterpret_cast<const float2*>(rrow + 0);
    const float2 rb = *reinterpret_cast<const float2*>(rrow + 2);
    const float2 rc = *reinterpret_cast<const float2*>(rrow + 4);

    // ---- reductions: depth numerator + rgb sums ----
    float dsum = w0 * m0   + w1 * m1;
    float rs   = w0 * ra.x + w1 * rb.y;
    float gs   = w0 * ra.y + w1 * rc.x;
    float bs   = w0 * rb.x + w1 * rc.y;
    #pragma unroll
    for (int off = 16; off >= 1; off >>= 1) {
        dsum += __shfl_xor_sync(FULL, dsum, off);
        rs   += __shfl_xor_sync(FULL, rs,   off);
        gs   += __shfl_xor_sync(FULL, gs,   off);
        bs   += __shfl_xor_sync(FULL, bs,   off);
    }

    // total weight analytically from full optical depth (lane 31's c1)
    const float ctot = __shfl_sync(FULL, c1, 31);
    const float wsum = 1.0f - __expf(-ctot);
    const float inv  = 1.0f / (wsum + 1e-6f);

    // normalized cdf at this lane's two positions (registers only)
    const float cd0 = (1.0f - __expf(-c0)) * inv;
    const float cd1 = (1.0f - __expf(-c1)) * inv;
    float cprev = __shfl_up_sync(FULL, cd1, 1);     // cdf[2*lane - 1]
    if (lane == 0) cprev = 0.0f;

    // u-count boundaries for this lane's two intervals
    const int kS = count_u(cprev);   // first fine idx with pos >= 2*lane
    const int kM = count_u(cd0);     // first fine idx with pos >= 2*lane+1
    const int kE = count_u(cd1);     // first fine idx with pos >= 2*lane+2

    float* zrow = zs_out + (size_t)ray * NC;
    const int i0 = 2 * lane;
    const int i1 = i0 + 1;

    // ---- mids: rank = i + (# fine samples strictly before mid i) ----
    zrow[(i0 == 0) ? 0 : (i0 + kM)] = m0;
    zrow[i1 + kE] = m1;

    const float ustep = 0.9f / 127.0f;

    // ---- interval p = i0 : fine k in [kS, kM) ----
    {
        const float cb = cprev, ca = cd0;
        const float mb = (i0 == 0) ? m0 : (m0 - delta);
        const float dm = m0 - mb;                    // 0 when i0==0 -> fz = m0
        float d = ca - cb;
        const float rd = (d < 1e-5f) ? 1.0f : 1.0f / d;
        const int slotoff = (i0 == 0) ? 1 : i0;      // clamp(p,1,64)
        for (int k = kS; k < kM; ++k) {
            const float u = fmaf((float)k, ustep, 0.05f);
            zrow[k + slotoff] = fmaf((u - cb) * rd, dm, mb);
        }
    }
    // ---- interval p = i1 : fine k in [kM, kE) ----
    {
        const float cb = cd0, ca = cd1;
        float d = ca - cb;
        const float rd = (d < 1e-5f) ? 1.0f : 1.0f / d;
        for (int k = kM; k < kE; ++k) {
            const float u = fmaf((float)k, ustep, 0.05f);
            zrow[k + i1] = fmaf((u - cb) * rd, delta, m0);
        }
    }
    // ---- tail p = 64 (u >= cdf[63]): fz = mids[63], rank count = 64 ----
    if (lane == 31) {
        for (int k = kE; k < NF; ++k) zrow[k + NS] = m1;
    }

    // ---- scalar outputs ----
    if (lane == 0) {
        rgb_out[(size_t)ray * 3 + 0] = rs;
        rgb_out[(size_t)ray * 3 + 1] = gs;
        rgb_out[(size_t)ray * 3 + 2] = bs;
        depth_out[ray] = dsum / (wsum + 1e-8f);
        acc_out[ray]   = wsum;
    }
}

extern "C" void kernel_launch(void* const* d_in, const int* in_sizes, int n_in,
                              void* d_out, int out_size)
{
    const float* near_   = (const float*)d_in[0];
    const float* far_    = (const float*)d_in[1];
    const float* density = (const float*)d_in[2];
    const float* rgb     = (const float*)d_in[3];
    const int B = in_sizes[0];

    float* out   = (float*)d_out;
    float* zs    = out;                       // B * 192
    float* rgbo  = zs + (size_t)B * NC;       // B * 3
    float* depth = rgbo + (size_t)B * 3;      // B
    float* acc   = depth + B;                 // B

    const int blocks = (B + WPB - 1) / WPB;
    pdf_sampler_kernel<<<blocks, WPB * 32>>>(near_, far_, density, rgb,
                                             zs, rgbo, depth, acc, B);
}

// round 3
// speedup vs baseline: 1.5617x; 1.5340x over previous
#include <cuda_runtime.h>
#include <math.h>

#define NS 64          // coarse samples
#define NF 128         // fine samples
#define NC 192         // combined
#define WPB 8          // warps per block
#define FULL 0xffffffffu

// #{k in [0,128) : u_k < x}, u_k = 0.05 + k * (0.9/127)
__device__ __forceinline__ int count_u(float x) {
    int c = __float2int_ru((x - 0.05f) * (127.0f / 0.9f));
    return min(max(c, 0), NF);
}

__device__ __forceinline__ unsigned long long pack2(float lo, float hi) {
    unsigned long long r;
    asm("mov.b64 %0, {%1, %2};" : "=l"(r) : "f"(lo), "f"(hi));
    return r;
}
__device__ __forceinline__ void unpack2(unsigned long long v, float& lo, float& hi) {
    asm("mov.b64 {%0, %1}, %2;" : "=f"(lo), "=f"(hi) : "l"(v));
}
__device__ __forceinline__ unsigned long long addp(unsigned long long a, unsigned long long b) {
    unsigned long long r;
    asm("add.rn.f32x2 %0, %1, %2;" : "=l"(r) : "l"(a), "l"(b));
    return r;
}

__global__ __launch_bounds__(WPB * 32)
void pdf_sampler_kernel(const float* __restrict__ near_, const float* __restrict__ far_,
                        const float* __restrict__ density, const float* __restrict__ rgb,
                        float* __restrict__ zs_out, float* __restrict__ rgb_out,
                        float* __restrict__ depth_out, float* __restrict__ acc_out,
                        int B)
{
    __shared__ __align__(16) float s_z[WPB][NC];

    const int warp = threadIdx.x >> 5;
    const int lane = threadIdx.x & 31;
    const int ray  = blockIdx.x * WPB + warp;
    if (ray >= B) return;

    const float nr = near_[ray];
    const float fr = far_[ray];
    const float delta = (fr - nr) * (1.0f / NS);

    // ---- density: 2 elems per lane, coalesced float2 ----
    const float2 dv = *reinterpret_cast<const float2*>(density + (size_t)ray * NS + 2 * lane);
    const float e0 = dv.x * delta;
    const float e1 = dv.y * delta;

    // ---- warp inclusive prefix sum of optical depth (pair per lane) ----
    const float ps = e0 + e1;
    float s = ps;
    #pragma unroll
    for (int off = 1; off < 32; off <<= 1) {
        float v = __shfl_up_sync(FULL, s, off);
        if (lane >= off) s += v;
    }
    const float excl = s - ps;           // cum optical depth before elem 2*lane
    const float c0 = excl + e0;          // inclusive at 2*lane
    const float c1 = excl + ps;          // inclusive at 2*lane+1

    // weights: w_i = T_i * (1 - exp(-x_i))
    const float T0 = __expf(-excl);
    const float w0 = T0 * (1.0f - __expf(-e0));
    const float Tm = T0 - w0;            // = T0 * exp(-e0)
    const float w1 = Tm * (1.0f - __expf(-e1));

    // analytic mids
    const float m0 = fmaf((float)(2 * lane) + 0.5f, delta, nr);
    const float m1 = m0 + delta;

    // ---- rgb loads (6 contiguous floats per lane, coalesced) ----
    const float* rrow = rgb + (size_t)ray * (NS * 3) + 6 * lane;
    const float2 ra = *reinterpret_cast<const float2*>(rrow + 0);
    const float2 rb = *reinterpret_cast<const float2*>(rrow + 2);
    const float2 rc = *reinterpret_cast<const float2*>(rrow + 4);

    // ---- reductions (packed f32x2 butterflies): (rs,gs) and (bs,dsum) ----
    unsigned long long p0 = pack2(w0 * ra.x + w1 * rb.y,   // rs
                                  w0 * ra.y + w1 * rc.x);  // gs
    unsigned long long p1 = pack2(w0 * rb.x + w1 * rc.y,   // bs
                                  w0 * m0   + w1 * m1);    // dsum
    #pragma unroll
    for (int off = 16; off >= 1; off >>= 1) {
        p0 = addp(p0, __shfl_xor_sync(FULL, p0, off));
        p1 = addp(p1, __shfl_xor_sync(FULL, p1, off));
    }

    // total weight analytically from full optical depth (lane 31's c1)
    const float ctot = __shfl_sync(FULL, c1, 31);
    const float wsum = 1.0f - __expf(-ctot);
    const float inv  = __fdividef(1.0f, wsum + 1e-6f);

    // normalized cdf at this lane's two positions (registers only)
    const float cd0 = (1.0f - __expf(-c0)) * inv;
    const float cd1 = (1.0f - __expf(-c1)) * inv;
    float cprev = __shfl_up_sync(FULL, cd1, 1);     // cdf[2*lane - 1]
    if (lane == 0) cprev = 0.0f;

    // u-count boundaries for this lane's two intervals
    const int kS = count_u(cprev);   // first fine idx with pos >= 2*lane
    const int kM = count_u(cd0);     // first fine idx with pos >= 2*lane+1
    const int kE = count_u(cd1);     // first fine idx with pos >= 2*lane+2

    float* zw = s_z[warp];
    const int i0 = 2 * lane;
    const int i1 = i0 + 1;

    // ---- mids: rank = i + (# fine samples strictly before mid i) ----
    zw[(i0 == 0) ? 0 : (i0 + kM)] = m0;
    zw[i1 + kE] = m1;

    const float ustep = 0.9f / 127.0f;

    // ---- interval p = i0 : fine k in [kS, kM); z affine in k ----
    {
        const float cb = cprev;
        const float mb = (i0 == 0) ? m0 : (m0 - delta);
        const float dm = m0 - mb;                    // 0 when i0==0 -> fz = m0
        const float d  = cd0 - cb;
        const float rd = (d < 1e-5f) ? 1.0f : __fdividef(1.0f, d);
        const float g  = rd * dm;
        const float u0 = fmaf((float)kS, ustep, 0.05f);
        float z        = fmaf(u0 - cb, g, mb);
        const float dz = ustep * g;
        const int slotoff = (i0 == 0) ? 1 : i0;      // clamp(p,1,64)
        for (int k = kS; k < kM; ++k) { zw[k + slotoff] = z; z += dz; }
    }
    // ---- interval p = i1 : fine k in [kM, kE) ----
    {
        const float d  = cd1 - cd0;
        const float rd = (d < 1e-5f) ? 1.0f : __fdividef(1.0f, d);
        const float g  = rd * delta;
        const float u0 = fmaf((float)kM, ustep, 0.05f);
        float z        = fmaf(u0 - cd0, g, m0);
        const float dz = ustep * g;
        for (int k = kM; k < kE; ++k) { zw[k + i1] = z; z += dz; }
    }
    // ---- tail p = 64 (u >= cdf[63]): fz = mids[63], rank count = 64 ----
    if (lane == 31) {
        for (int k = kE; k < NF; ++k) zw[k + NS] = m1;
    }
    __syncwarp();

    // ---- coalesced vectorized write of the merged row ----
    float4* zv = reinterpret_cast<float4*>(zs_out + (size_t)ray * NC);
    const float4* sv = reinterpret_cast<const float4*>(zw);
    zv[lane] = sv[lane];                             // 32 float4 = 128 floats
    if (lane < 16) zv[32 + lane] = sv[32 + lane];    // remaining 64 floats

    // ---- scalar outputs ----
    if (lane == 0) {
        float rs, gs, bs, dsum;
        unpack2(p0, rs, gs);
        unpack2(p1, bs, dsum);
        rgb_out[(size_t)ray * 3 + 0] = rs;
        rgb_out[(size_t)ray * 3 + 1] = gs;
        rgb_out[(size_t)ray * 3 + 2] = bs;
        depth_out[ray] = __fdividef(dsum, wsum + 1e-8f);
        acc_out[ray]   = wsum;
    }
}

extern "C" void kernel_launch(void* const* d_in, const int* in_sizes, int n_in,
                              void* d_out, int out_size)
{
    const float* near_   = (const float*)d_in[0];
    const float* far_    = (const float*)d_in[1];
    const float* density = (const float*)d_in[2];
    const float* rgb     = (const float*)d_in[3];
    const int B = in_sizes[0];

    float* out   = (float*)d_out;
    float* zs    = out;                       // B * 192
    float* rgbo  = zs + (size_t)B * NC;       // B * 3
    float* depth = rgbo + (size_t)B * 3;      // B
    float* acc   = depth + B;                 // B

    const int blocks = (B + WPB - 1) / WPB;
    pdf_sampler_kernel<<<blocks, WPB * 32>>>(near_, far_, density, rgb,
                                             zs, rgbo, depth, acc, B);
}